// round 1
// baseline (speedup 1.0000x reference)
#include <cuda_runtime.h>
#include <cstdint>
#include <math.h>

#define TLEN 4096
#define HDIM 256

// ---------------- scratch (static device arrays; no allocation) ----------------
__device__ float g_xsf[TLEN * 1024];   // 16 MB  input-proj forward (reused per layer)
__device__ float g_xsb[TLEN * 1024];   // 16 MB  input-proj backward
__device__ float g_h1 [TLEN * 512];    // 8 MB   layer0 output [hf | hb]
__device__ float g_h2 [TLEN * 512];    // 8 MB   layer1 output
__device__ float g_z  [TLEN * 256];    // 4 MB   fc1 output
__device__ float g_e  [TLEN * 256];    // 4 MB   fc2 output
__device__ float g_nrm[TLEN];          // row norms of e

// ---------------- generic 128x128 SGEMM: C = A(MxK) * B(NxK)^T (+epilogue) ------
// mode 0: C += bias ; mode 1: relu(C + bias) ; mode 2: cosine-distance epilogue
__global__ __launch_bounds__(256, 1)
void gemm_k(const float* __restrict__ A, const float* __restrict__ B,
            const float* __restrict__ bias, const float* __restrict__ nrm,
            float* __restrict__ C, int M, int N, int K, int mode)
{
    __shared__ float As[16][128];
    __shared__ float Bs[16][128];

    const int tid = threadIdx.x;
    const int bm = blockIdx.y << 7;
    const int bn = blockIdx.x << 7;
    const int tx = tid & 15;        // 0..15  -> 8 cols each
    const int ty = tid >> 4;        // 0..15  -> 8 rows each
    const int lr = tid >> 2;        // 0..63  load row
    const int lc = (tid & 3) << 2;  // 0,4,8,12 load col (float4)

    const float* Ap = A + (size_t)(bm + lr) * K + lc;
    const float* Bp = B + (size_t)(bn + lr) * K + lc;

    float acc[8][8];
#pragma unroll
    for (int i = 0; i < 8; i++)
#pragma unroll
        for (int j = 0; j < 8; j++) acc[i][j] = 0.f;

    for (int k0 = 0; k0 < K; k0 += 16) {
        float4 a0 = *(const float4*)(Ap + k0);
        float4 a1 = *(const float4*)(Ap + (size_t)64 * K + k0);
        float4 b0 = *(const float4*)(Bp + k0);
        float4 b1 = *(const float4*)(Bp + (size_t)64 * K + k0);
        __syncthreads();   // previous tile fully consumed
        As[lc + 0][lr] = a0.x; As[lc + 1][lr] = a0.y; As[lc + 2][lr] = a0.z; As[lc + 3][lr] = a0.w;
        As[lc + 0][lr + 64] = a1.x; As[lc + 1][lr + 64] = a1.y; As[lc + 2][lr + 64] = a1.z; As[lc + 3][lr + 64] = a1.w;
        Bs[lc + 0][lr] = b0.x; Bs[lc + 1][lr] = b0.y; Bs[lc + 2][lr] = b0.z; Bs[lc + 3][lr] = b0.w;
        Bs[lc + 0][lr + 64] = b1.x; Bs[lc + 1][lr + 64] = b1.y; Bs[lc + 2][lr + 64] = b1.z; Bs[lc + 3][lr + 64] = b1.w;
        __syncthreads();
#pragma unroll
        for (int k = 0; k < 16; k++) {
            float aF[8], bF[8];
            float4 t0 = *(const float4*)&As[k][ty * 8];
            float4 t1 = *(const float4*)&As[k][ty * 8 + 4];
            float4 t2 = *(const float4*)&Bs[k][tx * 8];
            float4 t3 = *(const float4*)&Bs[k][tx * 8 + 4];
            aF[0] = t0.x; aF[1] = t0.y; aF[2] = t0.z; aF[3] = t0.w;
            aF[4] = t1.x; aF[5] = t1.y; aF[6] = t1.z; aF[7] = t1.w;
            bF[0] = t2.x; bF[1] = t2.y; bF[2] = t2.z; bF[3] = t2.w;
            bF[4] = t3.x; bF[5] = t3.y; bF[6] = t3.z; bF[7] = t3.w;
#pragma unroll
            for (int i = 0; i < 8; i++)
#pragma unroll
                for (int j = 0; j < 8; j++)
                    acc[i][j] = fmaf(aF[i], bF[j], acc[i][j]);
        }
    }

    // epilogue
    float cj[8];
    if (mode == 2) {
#pragma unroll
        for (int j = 0; j < 8; j++) cj[j] = nrm[bn + tx * 8 + j];
    } else {
#pragma unroll
        for (int j = 0; j < 8; j++) cj[j] = bias[bn + tx * 8 + j];
    }
#pragma unroll
    for (int i = 0; i < 8; i++) {
        const int row = bm + ty * 8 + i;
        float* Crow = C + (size_t)row * N + bn + tx * 8;
        if (mode == 2) {
            const float ni = nrm[row];
#pragma unroll
            for (int j = 0; j < 8; j++) {
                float v = acc[i][j] / (ni * cj[j]);
                v = fmaxf(v, 1e-6f);
                acc[i][j] = 1.f - v;
            }
        } else {
#pragma unroll
            for (int j = 0; j < 8; j++) {
                float v = acc[i][j] + cj[j];
                if (mode == 1) v = fmaxf(v, 0.f);
                acc[i][j] = v;
            }
        }
        *(float4*)(Crow)     = make_float4(acc[i][0], acc[i][1], acc[i][2], acc[i][3]);
        *(float4*)(Crow + 4) = make_float4(acc[i][4], acc[i][5], acc[i][6], acc[i][7]);
    }
}

// ---------------- row-norm kernel ----------------
__global__ void norm_k(const float* __restrict__ e, float* __restrict__ nrm)
{
    const int row  = blockIdx.x * 8 + (threadIdx.x >> 5);
    const int lane = threadIdx.x & 31;
    const float* p = e + (size_t)row * 256;
    float s = 0.f;
#pragma unroll
    for (int i = 0; i < 8; i++) { float v = p[lane + i * 32]; s += v * v; }
#pragma unroll
    for (int o = 16; o; o >>= 1) s += __shfl_xor_sync(0xffffffffu, s, o);
    if (lane == 0) nrm[row] = sqrtf(s);
}

// ---------------- LSTM scan: 2 clusters of 8 CTAs (fwd / bwd) ----------------
// Each CTA owns 32 hidden units (128 gate rows). Whh slice lives in REGISTERS
// (64 fp32 per thread, 512 threads). h is broadcast cluster-wide each step via
// st.shared::cluster, visibility via barrier.cluster (release/acquire).
#define NCL 8
#define SCAN_THREADS 512

__device__ __forceinline__ uint32_t s2u(const void* p)
{
    uint32_t a;
    asm("{ .reg .u64 t; cvta.to.shared.u64 t, %1; cvt.u32.u64 %0, t; }" : "=r"(a) : "l"(p));
    return a;
}

__global__ void __cluster_dims__(NCL, 1, 1) __launch_bounds__(SCAN_THREADS, 1)
lstm_scan(const float* __restrict__ xsf, const float* __restrict__ xsb,
          const float* __restrict__ whf, const float* __restrict__ whb,
          float* __restrict__ hout)
{
    // padded h layout: 4 segments of 64 floats, stride 68 words -> conflict-free
    __shared__ float hsh[2][4 * 68];
    __shared__ float zsh[128];

    const int t   = threadIdx.x;
    const int dir = blockIdx.x / NCL;                 // 0 = forward, 1 = backward
    uint32_t rank;
    asm("mov.u32 %0, %%cluster_ctarank;" : "=r"(rank));

    const float* xs  = dir ? xsb : xsf;
    const float* Whh = dir ? whb : whf;

    const int r  = t >> 2;                // gate-row within CTA: 0..127
    const int q  = t & 3;                 // quarter of the dot product
    const int gg = r >> 5;                // gate index 0..3 (i,f,g,o)
    const int uu = r & 31;                // unit within CTA
    const int G  = gg * HDIM + (int)rank * 32 + uu;   // global gate row 0..1023

    // load this thread's 64 weights into registers (once)
    float4 w[16];
    const float4* wp = reinterpret_cast<const float4*>(Whh + (size_t)G * HDIM + q * 64);
#pragma unroll
    for (int i = 0; i < 16; i++) w[i] = wp[i];

    for (int i = t; i < 4 * 68; i += SCAN_THREADS) { hsh[0][i] = 0.f; hsh[1][i] = 0.f; }
    float creg = 0.f;
    __syncthreads();

    // prefetch xs for the first step
    float xnext = 0.f;
    if (q == 0) {
        const int trow0 = dir ? (TLEN - 1) : 0;
        xnext = xs[(size_t)trow0 * 1024 + G];
    }

    int par = 0;
    for (int s = 0; s < TLEN; s++) {
        const int trow = dir ? (TLEN - 1 - s) : s;
        const float xcur = xnext;
        if (q == 0 && s + 1 < TLEN) {
            const int tnext = dir ? (TLEN - 2 - s) : (s + 1);
            xnext = xs[(size_t)tnext * 1024 + G];
        }

        // z_partial = W_slice . h   (h broadcast from smem, weights in regs)
        const float4* hp = reinterpret_cast<const float4*>(&hsh[par][q * 68]);
        float acc = 0.f;
#pragma unroll
        for (int i = 0; i < 16; i++) {
            float4 hv = hp[i];
            acc = fmaf(w[i].x, hv.x, acc);
            acc = fmaf(w[i].y, hv.y, acc);
            acc = fmaf(w[i].z, hv.z, acc);
            acc = fmaf(w[i].w, hv.w, acc);
        }
        acc += __shfl_xor_sync(0xffffffffu, acc, 1);
        acc += __shfl_xor_sync(0xffffffffu, acc, 2);
        if (q == 0) zsh[r] = acc + xcur;
        __syncthreads();

        if (t < 32) {   // 32 "unit" threads: gates + state update + broadcast
            const float zi = zsh[t];
            const float zf = zsh[32 + t];
            const float zg = zsh[64 + t];
            const float zo = zsh[96 + t];
            const float si = 1.f / (1.f + expf(-zi));
            const float sf = 1.f / (1.f + expf(-zf));
            const float so = 1.f / (1.f + expf(-zo));
            const float c  = sf * creg + si * tanhf(zg);
            creg = c;
            const float h = so * tanhf(c);

            hout[(size_t)trow * 512 + dir * 256 + (int)rank * 32 + t] = h;

            const int j    = (int)rank * 32 + t;
            const int word = (j >> 6) * 68 + (j & 63);
            const uint32_t la = s2u(&hsh[par ^ 1][word]);
#pragma unroll
            for (int p = 0; p < NCL; p++) {
                uint32_t ra;
                asm volatile("mapa.shared::cluster.u32 %0, %1, %2;" : "=r"(ra) : "r"(la), "r"(p));
                asm volatile("st.shared::cluster.f32 [%0], %1;" :: "r"(ra), "f"(h));
            }
        }

        asm volatile("barrier.cluster.arrive.aligned;" ::: "memory");
        asm volatile("barrier.cluster.wait.aligned;"  ::: "memory");
        par ^= 1;
    }
}

// ---------------- launcher ----------------
extern "C" void kernel_launch(void* const* d_in, const int* in_sizes, int n_in,
                              void* d_out, int out_size)
{
    (void)in_sizes; (void)n_in; (void)out_size;
    const float* x     = (const float*)d_in[0];
    const float* wih0f = (const float*)d_in[1];
    const float* whh0f = (const float*)d_in[2];
    const float* b0f   = (const float*)d_in[3];
    const float* wih0b = (const float*)d_in[4];
    const float* whh0b = (const float*)d_in[5];
    const float* b0b   = (const float*)d_in[6];
    const float* wih1f = (const float*)d_in[7];
    const float* whh1f = (const float*)d_in[8];
    const float* b1f   = (const float*)d_in[9];
    const float* wih1b = (const float*)d_in[10];
    const float* whh1b = (const float*)d_in[11];
    const float* b1b   = (const float*)d_in[12];
    const float* fc1w  = (const float*)d_in[13];
    const float* fc1b  = (const float*)d_in[14];
    const float* fc2w  = (const float*)d_in[15];
    const float* fc2b  = (const float*)d_in[16];
    float* out = (float*)d_out;

    float *xsf, *xsb, *h1, *h2, *z, *e, *nrm;
    cudaGetSymbolAddress((void**)&xsf, g_xsf);
    cudaGetSymbolAddress((void**)&xsb, g_xsb);
    cudaGetSymbolAddress((void**)&h1,  g_h1);
    cudaGetSymbolAddress((void**)&h2,  g_h2);
    cudaGetSymbolAddress((void**)&z,   g_z);
    cudaGetSymbolAddress((void**)&e,   g_e);
    cudaGetSymbolAddress((void**)&nrm, g_nrm);

    const dim3 blk(256);

    // layer 0: input projections (M=4096, N=1024, K=128)
    gemm_k<<<dim3(8, 32), blk>>>(x, wih0f, b0f, nullptr, xsf, TLEN, 1024, 128, 0);
    gemm_k<<<dim3(8, 32), blk>>>(x, wih0b, b0b, nullptr, xsb, TLEN, 1024, 128, 0);
    // layer 0 scan
    lstm_scan<<<16, SCAN_THREADS>>>(xsf, xsb, whh0f, whh0b, h1);
    // layer 1: input projections (K=512)
    gemm_k<<<dim3(8, 32), blk>>>(h1, wih1f, b1f, nullptr, xsf, TLEN, 1024, 512, 0);
    gemm_k<<<dim3(8, 32), blk>>>(h1, wih1b, b1b, nullptr, xsb, TLEN, 1024, 512, 0);
    // layer 1 scan
    lstm_scan<<<16, SCAN_THREADS>>>(xsf, xsb, whh1f, whh1b, h2);
    // fc1 (relu), fc2
    gemm_k<<<dim3(2, 32), blk>>>(h2, fc1w, fc1b, nullptr, z, TLEN, 256, 512, 1);
    gemm_k<<<dim3(2, 32), blk>>>(z,  fc2w, fc2b, nullptr, e, TLEN, 256, 256, 0);
    // norms + cosine-distance matrix (fused epilogue)
    norm_k<<<TLEN / 8, 256>>>(e, nrm);
    gemm_k<<<dim3(32, 32), blk>>>(e, e, nullptr, nrm, out, TLEN, TLEN, 256, 2);
}

// round 2
// speedup vs baseline: 1.4982x; 1.4982x over previous
#include <cuda_runtime.h>
#include <cstdint>
#include <math.h>

#define TLEN 4096
#define HDIM 256

// ---------------- scratch (static device arrays; no allocation) ----------------
__device__ float g_xsf[TLEN * 1024];   // 16 MB  input-proj forward (reused per layer)
__device__ float g_xsb[TLEN * 1024];   // 16 MB  input-proj backward
__device__ float g_h1 [TLEN * 512];    // 8 MB   layer0 output [hf | hb]
__device__ float g_h2 [TLEN * 512];    // 8 MB   layer1 output
__device__ float g_z  [TLEN * 256];    // 4 MB   fc1 output
__device__ float g_e  [TLEN * 256];    // 4 MB   fc2 output
__device__ float g_nrm[TLEN];          // row norms of e

// ---------------- generic 128x128 SGEMM: C = A(MxK) * B(NxK)^T (+epilogue) ------
// mode 0: C += bias ; mode 1: relu(C + bias) ; mode 2: cosine-distance epilogue
__global__ __launch_bounds__(256, 1)
void gemm_k(const float* __restrict__ A, const float* __restrict__ B,
            const float* __restrict__ bias, const float* __restrict__ nrm,
            float* __restrict__ C, int M, int N, int K, int mode)
{
    __shared__ float As[16][128];
    __shared__ float Bs[16][128];

    const int tid = threadIdx.x;
    const int bm = blockIdx.y << 7;
    const int bn = blockIdx.x << 7;
    const int tx = tid & 15;        // 0..15  -> 8 cols each
    const int ty = tid >> 4;        // 0..15  -> 8 rows each
    const int lr = tid >> 2;        // 0..63  load row
    const int lc = (tid & 3) << 2;  // 0,4,8,12 load col (float4)

    const float* Ap = A + (size_t)(bm + lr) * K + lc;
    const float* Bp = B + (size_t)(bn + lr) * K + lc;

    float acc[8][8];
#pragma unroll
    for (int i = 0; i < 8; i++)
#pragma unroll
        for (int j = 0; j < 8; j++) acc[i][j] = 0.f;

    for (int k0 = 0; k0 < K; k0 += 16) {
        float4 a0 = *(const float4*)(Ap + k0);
        float4 a1 = *(const float4*)(Ap + (size_t)64 * K + k0);
        float4 b0 = *(const float4*)(Bp + k0);
        float4 b1 = *(const float4*)(Bp + (size_t)64 * K + k0);
        __syncthreads();   // previous tile fully consumed
        As[lc + 0][lr] = a0.x; As[lc + 1][lr] = a0.y; As[lc + 2][lr] = a0.z; As[lc + 3][lr] = a0.w;
        As[lc + 0][lr + 64] = a1.x; As[lc + 1][lr + 64] = a1.y; As[lc + 2][lr + 64] = a1.z; As[lc + 3][lr + 64] = a1.w;
        Bs[lc + 0][lr] = b0.x; Bs[lc + 1][lr] = b0.y; Bs[lc + 2][lr] = b0.z; Bs[lc + 3][lr] = b0.w;
        Bs[lc + 0][lr + 64] = b1.x; Bs[lc + 1][lr + 64] = b1.y; Bs[lc + 2][lr + 64] = b1.z; Bs[lc + 3][lr + 64] = b1.w;
        __syncthreads();
#pragma unroll
        for (int k = 0; k < 16; k++) {
            float aF[8], bF[8];
            float4 t0 = *(const float4*)&As[k][ty * 8];
            float4 t1 = *(const float4*)&As[k][ty * 8 + 4];
            float4 t2 = *(const float4*)&Bs[k][tx * 8];
            float4 t3 = *(const float4*)&Bs[k][tx * 8 + 4];
            aF[0] = t0.x; aF[1] = t0.y; aF[2] = t0.z; aF[3] = t0.w;
            aF[4] = t1.x; aF[5] = t1.y; aF[6] = t1.z; aF[7] = t1.w;
            bF[0] = t2.x; bF[1] = t2.y; bF[2] = t2.z; bF[3] = t2.w;
            bF[4] = t3.x; bF[5] = t3.y; bF[6] = t3.z; bF[7] = t3.w;
#pragma unroll
            for (int i = 0; i < 8; i++)
#pragma unroll
                for (int j = 0; j < 8; j++)
                    acc[i][j] = fmaf(aF[i], bF[j], acc[i][j]);
        }
    }

    // epilogue
    float cj[8];
    if (mode == 2) {
#pragma unroll
        for (int j = 0; j < 8; j++) cj[j] = nrm[bn + tx * 8 + j];
    } else {
#pragma unroll
        for (int j = 0; j < 8; j++) cj[j] = bias[bn + tx * 8 + j];
    }
#pragma unroll
    for (int i = 0; i < 8; i++) {
        const int row = bm + ty * 8 + i;
        float* Crow = C + (size_t)row * N + bn + tx * 8;
        if (mode == 2) {
            const float ni = nrm[row];
#pragma unroll
            for (int j = 0; j < 8; j++) {
                float v = acc[i][j] / (ni * cj[j]);
                v = fmaxf(v, 1e-6f);
                acc[i][j] = 1.f - v;
            }
        } else {
#pragma unroll
            for (int j = 0; j < 8; j++) {
                float v = acc[i][j] + cj[j];
                if (mode == 1) v = fmaxf(v, 0.f);
                acc[i][j] = v;
            }
        }
        *(float4*)(Crow)     = make_float4(acc[i][0], acc[i][1], acc[i][2], acc[i][3]);
        *(float4*)(Crow + 4) = make_float4(acc[i][4], acc[i][5], acc[i][6], acc[i][7]);
    }
}

// ---------------- row-norm kernel ----------------
__global__ void norm_k(const float* __restrict__ e, float* __restrict__ nrm)
{
    const int row  = blockIdx.x * 8 + (threadIdx.x >> 5);
    const int lane = threadIdx.x & 31;
    const float* p = e + (size_t)row * 256;
    float s = 0.f;
#pragma unroll
    for (int i = 0; i < 8; i++) { float v = p[lane + i * 32]; s += v * v; }
#pragma unroll
    for (int o = 16; o; o >>= 1) s += __shfl_xor_sync(0xffffffffu, s, o);
    if (lane == 0) nrm[row] = sqrtf(s);
}

// ---------------- LSTM scan helpers ----------------
#define NCL 8
#define SCAN_THREADS 512

__device__ __forceinline__ uint32_t s2u(const void* p)
{
    uint32_t a;
    asm("{ .reg .u64 t; cvta.to.shared.u64 t, %1; cvt.u32.u64 %0, t; }" : "=r"(a) : "l"(p));
    return a;
}
__device__ __forceinline__ uint32_t mapa_u32(uint32_t la, uint32_t rank)
{
    uint32_t ra;
    asm("mapa.shared::cluster.u32 %0, %1, %2;" : "=r"(ra) : "r"(la), "r"(rank));
    return ra;
}
__device__ __forceinline__ void st_async_f32(uint32_t ra_data, float v, uint32_t ra_bar)
{
    asm volatile("st.async.shared::cluster.mbarrier::complete_tx::bytes.u32 [%0], %1, [%2];"
                 :: "r"(ra_data), "r"(__float_as_uint(v)), "r"(ra_bar) : "memory");
}
__device__ __forceinline__ void mbar_init(uint32_t bar, uint32_t cnt)
{
    asm volatile("mbarrier.init.shared.b64 [%0], %1;" :: "r"(bar), "r"(cnt) : "memory");
}
__device__ __forceinline__ void mbar_expect(uint32_t bar, uint32_t bytes)
{
    asm volatile("mbarrier.arrive.expect_tx.shared.b64 _, [%0], %1;" :: "r"(bar), "r"(bytes) : "memory");
}
__device__ __forceinline__ void mbar_wait(uint32_t bar, uint32_t phase)
{
    asm volatile(
        "{\n\t"
        ".reg .pred P%=;\n\t"
        "W%=:\n\t"
        "mbarrier.try_wait.parity.acquire.cta.shared::cta.b64 P%=, [%0], %1, 0x989680;\n\t"
        "@P%= bra.uni D%=;\n\t"
        "bra.uni W%=;\n\t"
        "D%=:\n\t"
        "}"
        :: "r"(bar), "r"(phase) : "memory");
}
__device__ __forceinline__ float tanha(float x)
{
    float y; asm("tanh.approx.f32 %0, %1;" : "=f"(y) : "f"(x)); return y;
}
__device__ __forceinline__ float sigm(float x)
{
    return fmaf(tanha(0.5f * x), 0.5f, 0.5f);
}
__device__ __forceinline__ void fma2(unsigned long long& acc, unsigned long long a, unsigned long long b)
{
    asm("fma.rn.f32x2 %0, %1, %2, %3;" : "=l"(acc) : "l"(a), "l"(b), "l"(acc));
}

// ---------------- LSTM scan: 2 clusters of 8 CTAs (fwd / bwd) ----------------
// Each CTA owns 32 hidden units (128 gate rows). Whh slice lives in REGISTERS
// as packed f32x2. h is pushed cluster-wide each step via st.async (remote smem
// store + mbarrier complete_tx); consumers wait only on byte arrival — no
// cluster barrier on the critical path.
__global__ void __cluster_dims__(NCL, 1, 1) __launch_bounds__(SCAN_THREADS, 1)
lstm_scan(const float* __restrict__ xsf, const float* __restrict__ xsb,
          const float* __restrict__ whf, const float* __restrict__ whb,
          float* __restrict__ hout)
{
    // padded h layout: 4 segments of 64 floats, stride 68 words -> conflict-free
    __shared__ __align__(16) float hsh[2][4 * 68];
    __shared__ float zsh[128];
    __shared__ __align__(8) unsigned long long mbar[2];

    const int t   = threadIdx.x;
    const int dir = blockIdx.x / NCL;                 // 0 = forward, 1 = backward
    uint32_t rank;
    asm("mov.u32 %0, %%cluster_ctarank;" : "=r"(rank));

    const float* xs  = dir ? xsb : xsf;
    const float* Whh = dir ? whb : whf;

    const int r  = t >> 2;                // gate-row within CTA: 0..127
    const int q  = t & 3;                 // quarter of the dot product
    const int gg = r >> 5;                // gate index 0..3 (i,f,g,o)
    const int uu = r & 31;                // unit within CTA
    const int G  = gg * HDIM + (int)rank * 32 + uu;   // global gate row 0..1023

    // load this thread's 64 weights into registers as packed f32x2 pairs
    ulonglong2 wv[8];
    const ulonglong2* wp = reinterpret_cast<const ulonglong2*>(Whh + (size_t)G * HDIM + q * 64);
#pragma unroll
    for (int i = 0; i < 8; i++) wv[i] = wp[i];
    // second half
    ulonglong2 wv2[8];
#pragma unroll
    for (int i = 0; i < 8; i++) wv2[i] = wp[8 + i];

    for (int i = t; i < 4 * 68; i += SCAN_THREADS) { hsh[0][i] = 0.f; hsh[1][i] = 0.f; }

    const uint32_t bar0 = s2u(&mbar[0]);
    const uint32_t bar1 = s2u(&mbar[1]);
    if (t == 0) {
        mbar_init(bar0, 1);
        mbar_init(bar1, 1);
        mbar_expect(bar0, 1024);
        mbar_expect(bar1, 1024);
    }
    float creg = 0.f;
    __syncthreads();
    // all CTAs' barriers must be live before any remote st.async
    asm volatile("barrier.cluster.arrive.aligned;" ::: "memory");
    asm volatile("barrier.cluster.wait.aligned;"  ::: "memory");

    // prefetch xs for the first step
    float xnext = 0.f;
    if (q == 0) {
        const int trow0 = dir ? (TLEN - 1) : 0;
        xnext = xs[(size_t)trow0 * 1024 + G];
    }

    // per-writer constant: smem word index of this unit's h slot
    uint32_t la_d0 = 0, la_d1 = 0;
    if (t < 32) {
        const int j    = (int)rank * 32 + t;
        const int word = (j >> 6) * 68 + (j & 63);
        la_d0 = s2u(&hsh[0][word]);
        la_d1 = s2u(&hsh[1][word]);
    }

    int ph0 = 0, ph1 = 0;
    for (int s = 0; s < TLEN; s++) {
        const int rb = (s + 1) & 1;        // buffer holding h(s-1)
        const int wb = s & 1;              // buffer receiving h(s)
        if (s > 0) {
            if (rb == 0) { mbar_wait(bar0, ph0); ph0 ^= 1; if (t == 0) mbar_expect(bar0, 1024); }
            else         { mbar_wait(bar1, ph1); ph1 ^= 1; if (t == 0) mbar_expect(bar1, 1024); }
        }

        const int trow = dir ? (TLEN - 1 - s) : s;
        const float xcur = xnext;
        if (q == 0 && s + 1 < TLEN) {
            const int tnext = dir ? (TLEN - 2 - s) : (s + 1);
            xnext = xs[(size_t)tnext * 1024 + G];
        }

        // z_partial = W_slice . h(s-1): packed f32x2 FMAs, h loaded as b64 pairs
        const ulonglong2* hp = reinterpret_cast<const ulonglong2*>(&hsh[rb][q * 68]);
        unsigned long long acc2 = 0ull;
#pragma unroll
        for (int i = 0; i < 8; i++) {
            ulonglong2 hv = hp[i];
            fma2(acc2, wv[i].x, hv.x);
            fma2(acc2, wv[i].y, hv.y);
        }
#pragma unroll
        for (int i = 0; i < 8; i++) {
            ulonglong2 hv = hp[8 + i];
            fma2(acc2, wv2[i].x, hv.x);
            fma2(acc2, wv2[i].y, hv.y);
        }
        float alo, ahi;
        asm("mov.b64 {%0, %1}, %2;" : "=f"(alo), "=f"(ahi) : "l"(acc2));
        float acc = alo + ahi;
        acc += __shfl_xor_sync(0xffffffffu, acc, 1);
        acc += __shfl_xor_sync(0xffffffffu, acc, 2);
        if (q == 0) zsh[r] = acc + xcur;
        __syncthreads();

        if (t < 32) {   // 32 "unit" threads: gates + state update + broadcast
            const float zi = zsh[t];
            const float zf = zsh[32 + t];
            const float zg = zsh[64 + t];
            const float zo = zsh[96 + t];
            const float si = sigm(zi);
            const float sf = sigm(zf);
            const float so = sigm(zo);
            const float c  = sf * creg + si * tanha(zg);
            creg = c;
            const float h = so * tanha(c);

            hout[(size_t)trow * 512 + dir * 256 + (int)rank * 32 + t] = h;

            if (s + 1 < TLEN) {
                const uint32_t la_d = wb ? la_d1 : la_d0;
                const uint32_t la_b = wb ? bar1 : bar0;
#pragma unroll
                for (int p = 0; p < NCL; p++) {
                    const uint32_t ra_d = mapa_u32(la_d, p);
                    const uint32_t ra_b = mapa_u32(la_b, p);
                    st_async_f32(ra_d, h, ra_b);
                }
            }
        }
    }

    // don't exit while peers may still be consuming our last stores
    asm volatile("barrier.cluster.arrive.aligned;" ::: "memory");
    asm volatile("barrier.cluster.wait.aligned;"  ::: "memory");
}

// ---------------- launcher ----------------
extern "C" void kernel_launch(void* const* d_in, const int* in_sizes, int n_in,
                              void* d_out, int out_size)
{
    (void)in_sizes; (void)n_in; (void)out_size;
    const float* x     = (const float*)d_in[0];
    const float* wih0f = (const float*)d_in[1];
    const float* whh0f = (const float*)d_in[2];
    const float* b0f   = (const float*)d_in[3];
    const float* wih0b = (const float*)d_in[4];
    const float* whh0b = (const float*)d_in[5];
    const float* b0b   = (const float*)d_in[6];
    const float* wih1f = (const float*)d_in[7];
    const float* whh1f = (const float*)d_in[8];
    const float* b1f   = (const float*)d_in[9];
    const float* wih1b = (const float*)d_in[10];
    const float* whh1b = (const float*)d_in[11];
    const float* b1b   = (const float*)d_in[12];
    const float* fc1w  = (const float*)d_in[13];
    const float* fc1b  = (const float*)d_in[14];
    const float* fc2w  = (const float*)d_in[15];
    const float* fc2b  = (const float*)d_in[16];
    float* out = (float*)d_out;

    float *xsf, *xsb, *h1, *h2, *z, *e, *nrm;
    cudaGetSymbolAddress((void**)&xsf, g_xsf);
    cudaGetSymbolAddress((void**)&xsb, g_xsb);
    cudaGetSymbolAddress((void**)&h1,  g_h1);
    cudaGetSymbolAddress((void**)&h2,  g_h2);
    cudaGetSymbolAddress((void**)&z,   g_z);
    cudaGetSymbolAddress((void**)&e,   g_e);
    cudaGetSymbolAddress((void**)&nrm, g_nrm);

    const dim3 blk(256);

    // layer 0: input projections (M=4096, N=1024, K=128)
    gemm_k<<<dim3(8, 32), blk>>>(x, wih0f, b0f, nullptr, xsf, TLEN, 1024, 128, 0);
    gemm_k<<<dim3(8, 32), blk>>>(x, wih0b, b0b, nullptr, xsb, TLEN, 1024, 128, 0);
    // layer 0 scan
    lstm_scan<<<16, SCAN_THREADS>>>(xsf, xsb, whh0f, whh0b, h1);
    // layer 1: input projections (K=512)
    gemm_k<<<dim3(8, 32), blk>>>(h1, wih1f, b1f, nullptr, xsf, TLEN, 1024, 512, 0);
    gemm_k<<<dim3(8, 32), blk>>>(h1, wih1b, b1b, nullptr, xsb, TLEN, 1024, 512, 0);
    // layer 1 scan
    lstm_scan<<<16, SCAN_THREADS>>>(xsf, xsb, whh1f, whh1b, h2);
    // fc1 (relu), fc2
    gemm_k<<<dim3(2, 32), blk>>>(h2, fc1w, fc1b, nullptr, z, TLEN, 256, 512, 1);
    gemm_k<<<dim3(2, 32), blk>>>(z,  fc2w, fc2b, nullptr, e, TLEN, 256, 256, 0);
    // norms + cosine-distance matrix (fused epilogue)
    norm_k<<<TLEN / 8, 256>>>(e, nrm);
    gemm_k<<<dim3(32, 32), blk>>>(e, e, nullptr, nrm, out, TLEN, TLEN, 256, 2);
}